// round 7
// baseline (speedup 1.0000x reference)
#include <cuda_runtime.h>
#include <cstdint>
#include <math.h>

#define VOC 4096
#define EMBD 256
#define HID 512
#define BB  64
#define TT  1024
#define G4H 2048
#define BT  (BB*TT)                       // 65536
#define BTV ((long long)BT*VOC)           // 268435456

typedef unsigned long long ull;

// ---------------- static device scratch (no runtime allocation) ----------------
__device__ __align__(16) float g_G[(size_t)VOC*G4H];   // 32 MB : emb@W_ih^T + (b_ih+b_hh)
__device__ __align__(16) float g_hs[(size_t)BT*HID];   // 128 MB: hidden states, row (t*64+b)
__device__ __align__(16) float g_h[2][BB*HID];         // double-buffered h, layout [b][k]
__device__ ull      g_amax[BT];                        // packed (float,idx) argmax per row
__device__ unsigned g_ctr[TT];                         // grid barrier arrival counters
__device__ int      g_xmode;                           // 1 = x is int32, 0 = x is int64

// ---------------- packed f32x2 helpers ----------------
__device__ __forceinline__ void fma2(ull& d, ull a, ull b){
    asm("fma.rn.f32x2 %0, %1, %2, %0;" : "+l"(d) : "l"(a), "l"(b));
}
__device__ __forceinline__ ull pk2(float x, float y){
    ull r; asm("mov.b64 %0, {%1,%2};" : "=l"(r) : "f"(x), "f"(y)); return r;
}
__device__ __forceinline__ float2 up2(ull v){
    float2 r; asm("mov.b64 {%0,%1}, %2;" : "=f"(r.x), "=f"(r.y) : "l"(v)); return r;
}
// monotone float->u32; pack with complemented index so max => (max val, lowest idx)
__device__ __forceinline__ ull packam(float v, int n){
    unsigned u = __float_as_uint(v);
    u = (u & 0x80000000u) ? ~u : (u | 0x80000000u);
    return ((ull)u << 32) | (unsigned)(VOC - 1 - n);
}

// ---------------- dtype detect + init (every replay) ----------------
__global__ void detect_k(const int* __restrict__ x32){
    if (threadIdx.x == 0){
        int nz = 0;
        for (int i = 0; i < 128; i++) nz += (x32[2*i + 1] != 0);
        g_xmode = (nz > 0) ? 1 : 0;   // all-odd-words-zero => little-endian int64 tokens
    }
}
__global__ void init_k(){
    int i = blockIdx.x*blockDim.x + threadIdx.x;
    int n = blockDim.x*gridDim.x;
    for (int p = i; p < BB*HID; p += n) g_h[0][p] = 0.f;
    for (int p = i; p < BT;     p += n) g_amax[p] = 0ull;
    for (int p = i; p < TT;     p += n) g_ctr[p] = 0u;
}

// ---------------- generic SGEMM-NT: C[m][n] = sum_k A[m][k]*B[n][k] + bias ------
// BM=BN=128, BK=16, 256 threads, 8x8 micro-tile via f32x2.
// flags: 1 = write C, 2 = permute out row m -> (m%64)*TT + m/64, 4 = fused argmax
__global__ __launch_bounds__(256, 2) void gemm_k(
    const float* __restrict__ A, const float* __restrict__ B,
    const float* __restrict__ bias1, const float* __restrict__ bias2,
    float* __restrict__ C, int M, int N, int K, int flags)
{
    __shared__ __align__(16) float smem[2*16*132];
    float* As = smem;
    float* Bs = smem + 16*132;
    const int m0 = blockIdx.x*128, n0 = blockIdx.y*128;
    const int tid = threadIdx.x;
    const int tm = tid >> 4, tn = tid & 15;

    ull acc[8][4];
    #pragma unroll
    for (int i = 0; i < 8; i++)
        #pragma unroll
        for (int j = 0; j < 4; j++) acc[i][j] = 0ull;

    for (int kt = 0; kt < K; kt += 16){
        #pragma unroll
        for (int l = 0; l < 2; l++){
            int idx = tid + l*256;           // 0..511 over 128 rows x 4 float4
            int row = idx >> 2, kq = idx & 3;
            float4 va = *(const float4*)(A + (size_t)(m0+row)*K + kt + kq*4);
            float4 vb = *(const float4*)(B + (size_t)(n0+row)*K + kt + kq*4);
            As[(kq*4+0)*132+row] = va.x; As[(kq*4+1)*132+row] = va.y;
            As[(kq*4+2)*132+row] = va.z; As[(kq*4+3)*132+row] = va.w;
            Bs[(kq*4+0)*132+row] = vb.x; Bs[(kq*4+1)*132+row] = vb.y;
            Bs[(kq*4+2)*132+row] = vb.z; Bs[(kq*4+3)*132+row] = vb.w;
        }
        __syncthreads();
        #pragma unroll
        for (int k = 0; k < 16; k++){
            const float* ap = &As[k*132 + tm*8];
            float4 a0 = *(const float4*)ap;
            float4 a1 = *(const float4*)(ap + 4);
            const ulonglong2* bp = (const ulonglong2*)&Bs[k*132 + tn*8];
            ulonglong2 bq0 = bp[0], bq1 = bp[1];
            ull bb0 = bq0.x, bb1 = bq0.y, bb2 = bq1.x, bb3 = bq1.y;
            float aa[8] = {a0.x,a0.y,a0.z,a0.w,a1.x,a1.y,a1.z,a1.w};
            #pragma unroll
            for (int i = 0; i < 8; i++){
                ull ad = pk2(aa[i], aa[i]);
                fma2(acc[i][0], ad, bb0); fma2(acc[i][1], ad, bb1);
                fma2(acc[i][2], ad, bb2); fma2(acc[i][3], ad, bb3);
            }
        }
        __syncthreads();
    }

    float bv[8];
    {
        const float* b1p = bias1 + n0 + tn*8;
        #pragma unroll
        for (int c = 0; c < 8; c++) bv[c] = b1p[c];
        if (bias2){
            const float* b2p = bias2 + n0 + tn*8;
            #pragma unroll
            for (int c = 0; c < 8; c++) bv[c] += b2p[c];
        }
    }
    const bool wr = flags & 1, pm = flags & 2, am = flags & 4;
    ull best[8];
    #pragma unroll
    for (int i = 0; i < 8; i++){
        int m = m0 + tm*8 + i;
        float v[8];
        #pragma unroll
        for (int jp = 0; jp < 4; jp++){
            float2 f = up2(acc[i][jp]);
            v[2*jp]   = f.x + bv[2*jp];
            v[2*jp+1] = f.y + bv[2*jp+1];
        }
        if (wr){
            size_t orow = pm ? (size_t)((m & 63)*TT + (m >> 6)) : (size_t)m;
            float4* dst = (float4*)(C + orow*(size_t)N + n0 + tn*8);
            dst[0] = make_float4(v[0],v[1],v[2],v[3]);
            dst[1] = make_float4(v[4],v[5],v[6],v[7]);
        }
        if (am){
            ull bl = packam(v[0], n0 + tn*8);
            #pragma unroll
            for (int c = 1; c < 8; c++){
                ull p = packam(v[c], n0 + tn*8 + c);
                if (p > bl) bl = p;
            }
            best[i] = bl;
        }
    }
    if (am){
        __syncthreads();
        ull* red = (ull*)smem;               // 128*16 ull = 16384 B <= 16896 B
        #pragma unroll
        for (int i = 0; i < 8; i++) red[(tm*8+i)*16 + tn] = best[i];
        __syncthreads();
        if (tid < 128){
            ull b = red[tid*16];
            #pragma unroll
            for (int c = 1; c < 16; c++){
                ull p = red[tid*16 + c];
                if (p > b) b = p;
            }
            atomicMax(&g_amax[m0 + tid], b);
        }
    }
}

// ---------------- persistent LSTM recurrence: 128 blocks x 256 threads ----------
// Block owns 4 hidden units (16 gate rows). W_hh held in REGISTERS (4x32 floats
// per thread). k split across 16 lanes, reduced via 16-lane shfl butterfly.
// h staged to smem each step from global (XOR-swizzled chunks). c kept in regs.
// smem: h_s 64*2048B (swizzled) + gbuf 16*64 floats
#define SM_LSTM (64*2048 + 16*64*4)
__global__ __launch_bounds__(256, 1) void lstm_k(const void* __restrict__ xraw,
                                                 const float* __restrict__ Whh)
{
    extern __shared__ char sm[];
    float* gbuf = (float*)(sm + 64*2048);
    const int tid  = threadIdx.x;
    const int j0   = blockIdx.x * 4;
    const int bg   = tid >> 6;          // 4 batch groups of 16
    const int gate = (tid >> 4) & 3;    // i,f,g,o
    const int ks   = tid & 15;          // k-slice of 32
    const int ks7  = ks & 7;
    const int xmode = g_xmode;

    // epilogue mapping: thread owns (eb, ejj) every step -> c in register
    const int eb  = tid >> 2;
    const int ejj = tid & 3;
    const int ej  = j0 + ejj;
    float c_reg = 0.f;

    // ---- load W_hh slice into registers (once per launch) ----
    ull w0[16], w1[16], w2[16], w3[16];
    {
        const float* base = Whh + (size_t)(gate*HID + j0)*HID + ks*32;
        #pragma unroll
        for (int i = 0; i < 8; i++){
            float4 a = *(const float4*)(base + 0*HID + i*4);
            float4 b = *(const float4*)(base + 1*HID + i*4);
            float4 c = *(const float4*)(base + 2*HID + i*4);
            float4 d = *(const float4*)(base + 3*HID + i*4);
            w0[2*i] = pk2(a.x,a.y); w0[2*i+1] = pk2(a.z,a.w);
            w1[2*i] = pk2(b.x,b.y); w1[2*i+1] = pk2(b.z,b.w);
            w2[2*i] = pk2(c.x,c.y); w2[2*i+1] = pk2(c.z,c.w);
            w3[2*i] = pk2(d.x,d.y); w3[2*i+1] = pk2(d.z,d.w);
        }
    }

    volatile unsigned* vctr = (volatile unsigned*)g_ctr;

    for (int t = 0; t < TT; t++){
        // ---- stage h_t (global -> swizzled smem), L2 reads (bypass stale L1) ----
        const float* hg = g_h[t & 1];
        #pragma unroll
        for (int l = 0; l < 32; l++){
            int idx = tid + l*256;          // 8192 float4: b = idx>>7, chunk q = idx&127
            int b = idx >> 7, q = idx & 127;
            float4 v = __ldcg((const float4*)(hg + b*HID + q*4));
            *(float4*)(sm + b*2048 + ((q ^ ((q >> 3) & 7)) << 4)) = v;
        }
        __syncthreads();

        // ---- 16 gate rows x 64 b dot products ----
        #pragma unroll 2
        for (int bi = 0; bi < 16; bi++){
            int b = bg*16 + bi;
            const char* hb = sm + b*2048;
            ull a0 = 0ull, a1 = 0ull, a2 = 0ull, a3 = 0ull;
            #pragma unroll
            for (int i = 0; i < 8; i++){
                ulonglong2 hv = *(const ulonglong2*)(hb + ((ks*8 + (i ^ ks7)) << 4));
                fma2(a0, hv.x, w0[2*i]); fma2(a0, hv.y, w0[2*i+1]);
                fma2(a1, hv.x, w1[2*i]); fma2(a1, hv.y, w1[2*i+1]);
                fma2(a2, hv.x, w2[2*i]); fma2(a2, hv.y, w2[2*i+1]);
                fma2(a3, hv.x, w3[2*i]); fma2(a3, hv.y, w3[2*i+1]);
            }
            float2 p;
            p = up2(a0); float s0 = p.x + p.y;
            p = up2(a1); float s1 = p.x + p.y;
            p = up2(a2); float s2 = p.x + p.y;
            p = up2(a3); float s3 = p.x + p.y;
            #pragma unroll
            for (int off = 1; off < 16; off <<= 1){
                s0 += __shfl_xor_sync(0xFFFFFFFFu, s0, off, 32);
                s1 += __shfl_xor_sync(0xFFFFFFFFu, s1, off, 32);
                s2 += __shfl_xor_sync(0xFFFFFFFFu, s2, off, 32);
                s3 += __shfl_xor_sync(0xFFFFFFFFu, s3, off, 32);
            }
            if (ks == 0)
                *(float4*)(gbuf + b*16 + gate*4) = make_float4(s0,s1,s2,s3);
        }
        __syncthreads();

        // ---- epilogue: activations, c/h update ----
        {
            long long xv;
            if (xmode) xv = (long long)((const int*)xraw)[(size_t)eb*TT + t];
            else       xv = ((const long long*)xraw)[(size_t)eb*TT + t];
            xv &= (VOC - 1);
            const float* Gb = g_G + (size_t)xv * G4H;
            float di = gbuf[eb*16 + 0  + ejj] + Gb[ej];
            float df = gbuf[eb*16 + 4  + ejj] + Gb[HID   + ej];
            float dg = gbuf[eb*16 + 8  + ejj] + Gb[2*HID + ej];
            float dv = gbuf[eb*16 + 12 + ejj] + Gb[3*HID + ej];
            float si = 1.f/(1.f + expf(-di));
            float sf = 1.f/(1.f + expf(-df));
            float tg = tanhf(dg);
            float so = 1.f/(1.f + expf(-dv));
            c_reg = sf * c_reg + si * tg;
            float h = so * tanhf(c_reg);
            g_h[(t+1) & 1][eb*HID + ej] = h;
            g_hs[((size_t)t*BB + eb)*HID + ej] = h;
        }

        // ---- grid barrier (counters pre-zeroed by init_k each replay) ----
        __threadfence();
        __syncthreads();
        if (tid == 0){
            atomicAdd(&g_ctr[t], 1u);
            while (vctr[t] < 128u) { }
            __threadfence();
        }
        __syncthreads();
    }
}

// ---------------- decode argmax, write predictions --------------------------
__global__ void writer_k(float* out, long long out_size){
    int m = blockIdx.x*blockDim.x + threadIdx.x;
    if (m >= BT) return;
    int idx = VOC - 1 - (int)(g_amax[m] & 0xFFFFFFFFull);
    int b = m & 63, tt = m >> 6;
    long long orow = (long long)b*TT + tt;
    if (out_size >= BTV + BT){
        out[BTV + orow] = (float)idx;              // logits + preds concatenated (f32)
    } else if (out_size < BTV && out_size >= BT){
        if (g_xmode) ((int*)out)[orow] = idx;      // preds-only, int32 world
        else ((long long*)out)[orow] = (long long)idx; // preds-only, int64 world
    }
}

extern "C" void kernel_launch(void* const* d_in, const int* in_sizes, int n_in,
                              void* d_out, int out_size)
{
    const void* x        = d_in[0];
    // d_in[1] = lens : unused by the reference computation
    const float* emb     = (const float*)d_in[2];
    const float* W_ih    = (const float*)d_in[3];
    const float* W_hh    = (const float*)d_in[4];
    const float* b_ih    = (const float*)d_in[5];
    const float* b_hh    = (const float*)d_in[6];
    const float* W_proj  = (const float*)d_in[7];
    const float* b_proj  = (const float*)d_in[8];
    (void)in_sizes; (void)n_in;

    float *pG, *pHS;
    cudaGetSymbolAddress((void**)&pG,  g_G);
    cudaGetSymbolAddress((void**)&pHS, g_hs);
    cudaFuncSetAttribute(lstm_k,
                         cudaFuncAttributeMaxDynamicSharedMemorySize, SM_LSTM);

    detect_k<<<1, 32>>>((const int*)x);
    init_k<<<256, 256>>>();

    // G = emb @ W_ih^T + (b_ih + b_hh)   [4096 x 2048], K=256
    gemm_k<<<dim3(VOC/128, G4H/128), 256>>>(emb, W_ih, b_ih, b_hh, pG,
                                            VOC, G4H, EMBD, /*flags=*/1);

    // persistent LSTM recurrence (single kernel, grid-wide barrier per step)
    lstm_k<<<128, 256, SM_LSTM>>>(x, W_hh);

    // logits = hs @ W_proj^T + b_proj    [65536 x 4096], K=512 (+ fused argmax)
    int flags = 4 | 2 | (((long long)out_size >= BTV) ? 1 : 0);
    gemm_k<<<dim3(BT/128, VOC/128), 256>>>(pHS, W_proj, b_proj, nullptr,
                                           (float*)d_out, BT, VOC, HID, flags);

    writer_k<<<BT/256, 256>>>((float*)d_out, (long long)out_size);
}

// round 12
// speedup vs baseline: 1.0191x; 1.0191x over previous
#include <cuda_runtime.h>
#include <cstdint>
#include <math.h>

#define VOC 4096
#define EMBD 256
#define HID 512
#define BB  64
#define TT  1024
#define G4H 2048
#define BT  (BB*TT)                       // 65536
#define BTV ((long long)BT*VOC)           // 268435456

typedef unsigned long long ull;

// ---------------- static device scratch (no runtime allocation) ----------------
__device__ __align__(16) float g_G[(size_t)VOC*G4H];   // 32 MB : emb@W_ih^T + (b_ih+b_hh)
__device__ __align__(16) float g_hs[(size_t)BT*HID];   // 128 MB: hidden states, row (t*64+b)
__device__ __align__(16) float g_h[2][BB*HID];         // double-buffered h, layout [b][k]
__device__ ull      g_amax[BT];                        // packed (float,idx) argmax per row
__device__ unsigned g_ctr[TT];                         // grid barrier arrival counters
__device__ int      g_xmode;                           // 1 = x is int32, 0 = x is int64

// ---------------- packed f32x2 + sync helpers ----------------
__device__ __forceinline__ void fma2(ull& d, ull a, ull b){
    asm("fma.rn.f32x2 %0, %1, %2, %0;" : "+l"(d) : "l"(a), "l"(b));
}
__device__ __forceinline__ ull pk2(float x, float y){
    ull r; asm("mov.b64 %0, {%1,%2};" : "=l"(r) : "f"(x), "f"(y)); return r;
}
__device__ __forceinline__ float2 up2(ull v){
    float2 r; asm("mov.b64 {%0,%1}, %2;" : "=f"(r.x), "=f"(r.y) : "l"(v)); return r;
}
__device__ __forceinline__ float redux16(float v){
    v += __shfl_xor_sync(0xFFFFFFFFu, v, 1, 32);
    v += __shfl_xor_sync(0xFFFFFFFFu, v, 2, 32);
    v += __shfl_xor_sync(0xFFFFFFFFu, v, 4, 32);
    v += __shfl_xor_sync(0xFFFFFFFFu, v, 8, 32);
    return v;
}
__device__ __forceinline__ void arrive_release(unsigned* p){
    asm volatile("red.release.gpu.global.add.u32 [%0], 1;" :: "l"(p) : "memory");
}
__device__ __forceinline__ unsigned ld_acquire(const unsigned* p){
    unsigned v; asm volatile("ld.acquire.gpu.global.u32 %0, [%1];" : "=r"(v) : "l"(p) : "memory");
    return v;
}
// monotone float->u32; pack with complemented index so max => (max val, lowest idx)
__device__ __forceinline__ ull packam(float v, int n){
    unsigned u = __float_as_uint(v);
    u = (u & 0x80000000u) ? ~u : (u | 0x80000000u);
    return ((ull)u << 32) | (unsigned)(VOC - 1 - n);
}

// ---------------- dtype detect + init (every replay) ----------------
__global__ void detect_k(const int* __restrict__ x32){
    if (threadIdx.x == 0){
        int nz = 0;
        for (int i = 0; i < 128; i++) nz += (x32[2*i + 1] != 0);
        g_xmode = (nz > 0) ? 1 : 0;   // all-odd-words-zero => little-endian int64 tokens
    }
}
__global__ void init_k(){
    int i = blockIdx.x*blockDim.x + threadIdx.x;
    int n = blockDim.x*gridDim.x;
    for (int p = i; p < BB*HID; p += n) g_h[0][p] = 0.f;
    for (int p = i; p < BT;     p += n) g_amax[p] = 0ull;
    for (int p = i; p < TT;     p += n) g_ctr[p] = 0u;
}

// ---------------- SGEMM-NT with register double-buffering ----------------------
// BM=BN=128, BK=16, 256 threads, 8x8 micro-tile via f32x2.
// flags: 1 = write C, 2 = permute out row m -> (m%64)*TT + m/64, 4 = fused argmax
__global__ __launch_bounds__(256, 2) void gemm_k(
    const float* __restrict__ A, const float* __restrict__ B,
    const float* __restrict__ bias1, const float* __restrict__ bias2,
    float* __restrict__ C, int M, int N, int K, int flags)
{
    __shared__ __align__(16) float smem[2*16*132];
    float* As = smem;
    float* Bs = smem + 16*132;
    const int m0 = blockIdx.x*128, n0 = blockIdx.y*128;
    const int tid = threadIdx.x;
    const int tm = tid >> 4, tn = tid & 15;
    const int rowA = tid >> 2, kq = tid & 3;

    const float* Ap = A + (size_t)(m0 + rowA)*K + kq*4;
    const float* Bp = B + (size_t)(n0 + rowA)*K + kq*4;
    const size_t o64 = (size_t)64*K;

    ull acc[8][4];
    #pragma unroll
    for (int i = 0; i < 8; i++)
        #pragma unroll
        for (int j = 0; j < 4; j++) acc[i][j] = 0ull;

    // prologue: stage tile 0 into registers
    float4 va0 = *(const float4*)(Ap);
    float4 va1 = *(const float4*)(Ap + o64);
    float4 vb0 = *(const float4*)(Bp);
    float4 vb1 = *(const float4*)(Bp + o64);

    for (int kt = 0; kt < K; kt += 16){
        As[(kq*4+0)*132+rowA] = va0.x; As[(kq*4+1)*132+rowA] = va0.y;
        As[(kq*4+2)*132+rowA] = va0.z; As[(kq*4+3)*132+rowA] = va0.w;
        As[(kq*4+0)*132+rowA+64] = va1.x; As[(kq*4+1)*132+rowA+64] = va1.y;
        As[(kq*4+2)*132+rowA+64] = va1.z; As[(kq*4+3)*132+rowA+64] = va1.w;
        Bs[(kq*4+0)*132+rowA] = vb0.x; Bs[(kq*4+1)*132+rowA] = vb0.y;
        Bs[(kq*4+2)*132+rowA] = vb0.z; Bs[(kq*4+3)*132+rowA] = vb0.w;
        Bs[(kq*4+0)*132+rowA+64] = vb1.x; Bs[(kq*4+1)*132+rowA+64] = vb1.y;
        Bs[(kq*4+2)*132+rowA+64] = vb1.z; Bs[(kq*4+3)*132+rowA+64] = vb1.w;
        __syncthreads();

        if (kt + 16 < K){   // prefetch next tile (LDGs overlap the compute below)
            va0 = *(const float4*)(Ap + kt + 16);
            va1 = *(const float4*)(Ap + o64 + kt + 16);
            vb0 = *(const float4*)(Bp + kt + 16);
            vb1 = *(const float4*)(Bp + o64 + kt + 16);
        }

        #pragma unroll
        for (int k = 0; k < 16; k++){
            const float* ap = &As[k*132 + tm*8];
            float4 a0 = *(const float4*)ap;
            float4 a1 = *(const float4*)(ap + 4);
            const ulonglong2* bp = (const ulonglong2*)&Bs[k*132 + tn*8];
            ulonglong2 bq0 = bp[0], bq1 = bp[1];
            ull bb0 = bq0.x, bb1 = bq0.y, bb2 = bq1.x, bb3 = bq1.y;
            float aa[8] = {a0.x,a0.y,a0.z,a0.w,a1.x,a1.y,a1.z,a1.w};
            #pragma unroll
            for (int i = 0; i < 8; i++){
                ull ad = pk2(aa[i], aa[i]);
                fma2(acc[i][0], ad, bb0); fma2(acc[i][1], ad, bb1);
                fma2(acc[i][2], ad, bb2); fma2(acc[i][3], ad, bb3);
            }
        }
        __syncthreads();
    }

    float bv[8];
    {
        const float* b1p = bias1 + n0 + tn*8;
        #pragma unroll
        for (int c = 0; c < 8; c++) bv[c] = b1p[c];
        if (bias2){
            const float* b2p = bias2 + n0 + tn*8;
            #pragma unroll
            for (int c = 0; c < 8; c++) bv[c] += b2p[c];
        }
    }
    const bool wr = flags & 1, pm = flags & 2, am = flags & 4;
    ull best[8];
    #pragma unroll
    for (int i = 0; i < 8; i++){
        int m = m0 + tm*8 + i;
        float v[8];
        #pragma unroll
        for (int jp = 0; jp < 4; jp++){
            float2 f = up2(acc[i][jp]);
            v[2*jp]   = f.x + bv[2*jp];
            v[2*jp+1] = f.y + bv[2*jp+1];
        }
        if (wr){
            size_t orow = pm ? (size_t)((m & 63)*TT + (m >> 6)) : (size_t)m;
            float4* dst = (float4*)(C + orow*(size_t)N + n0 + tn*8);
            dst[0] = make_float4(v[0],v[1],v[2],v[3]);
            dst[1] = make_float4(v[4],v[5],v[6],v[7]);
        }
        if (am){
            ull bl = packam(v[0], n0 + tn*8);
            #pragma unroll
            for (int c = 1; c < 8; c++){
                ull p = packam(v[c], n0 + tn*8 + c);
                if (p > bl) bl = p;
            }
            best[i] = bl;
        }
    }
    if (am){
        __syncthreads();
        ull* red = (ull*)smem;               // 128*16 ull = 16384 B <= 16896 B
        #pragma unroll
        for (int i = 0; i < 8; i++) red[(tm*8+i)*16 + tn] = best[i];
        __syncthreads();
        if (tid < 128){
            ull b = red[tid*16];
            #pragma unroll
            for (int c = 1; c < 16; c++){
                ull p = red[tid*16 + c];
                if (p > b) b = p;
            }
            atomicMax(&g_amax[m0 + tid], b);
        }
    }
}

// ---------------- persistent LSTM recurrence: 128 blocks x 256 threads ----------
// Block owns 4 hidden units (16 gate rows). W_hh in registers. k split across 16
// lanes, reduced via 4-level shfl butterfly. Token + gate-bias gather prefetched
// before the compute loop. Release/acquire grid barrier per step.
#define SM_LSTM (64*2048 + 16*64*4)
__global__ __launch_bounds__(256, 1) void lstm_k(const void* __restrict__ xraw,
                                                 const float* __restrict__ Whh)
{
    extern __shared__ char sm[];
    float* gbuf = (float*)(sm + 64*2048);
    const int tid  = threadIdx.x;
    const int j0   = blockIdx.x * 4;
    const int bg   = tid >> 6;          // 4 batch groups of 16
    const int gate = (tid >> 4) & 3;    // i,f,g,o
    const int ks   = tid & 15;          // k-slice of 32
    const int ks7  = ks & 7;
    const int xmode = g_xmode;

    // epilogue mapping: thread owns (eb, ejj) every step -> c in register
    const int eb  = tid >> 2;
    const int ejj = tid & 3;
    const int ej  = j0 + ejj;
    float c_reg = 0.f;

    // ---- load W_hh slice into registers (once per launch) ----
    ull w0[16], w1[16], w2[16], w3[16];
    {
        const float* base = Whh + (size_t)(gate*HID + j0)*HID + ks*32;
        #pragma unroll
        for (int i = 0; i < 8; i++){
            float4 a = *(const float4*)(base + 0*HID + i*4);
            float4 b = *(const float4*)(base + 1*HID + i*4);
            float4 c = *(const float4*)(base + 2*HID + i*4);
            float4 d = *(const float4*)(base + 3*HID + i*4);
            w0[2*i] = pk2(a.x,a.y); w0[2*i+1] = pk2(a.z,a.w);
            w1[2*i] = pk2(b.x,b.y); w1[2*i+1] = pk2(b.z,b.w);
            w2[2*i] = pk2(c.x,c.y); w2[2*i+1] = pk2(c.z,c.w);
            w3[2*i] = pk2(d.x,d.y); w3[2*i+1] = pk2(d.z,d.w);
        }
    }

    for (int t = 0; t < TT; t++){
        // ---- stage h_t (global -> swizzled smem), L2 reads (bypass stale L1) ----
        const float* hg = g_h[t & 1];
        #pragma unroll
        for (int l = 0; l < 32; l++){
            int idx = tid + l*256;          // 8192 float4: b = idx>>7, chunk q = idx&127
            int b = idx >> 7, q = idx & 127;
            float4 v = __ldcg((const float4*)(hg + b*HID + q*4));
            *(float4*)(sm + b*2048 + ((q ^ ((q >> 3) & 7)) << 4)) = v;
        }
        __syncthreads();

        // ---- prefetch token + gate-bias gather (consumed in epilogue) ----
        long long xv;
        if (xmode) xv = (long long)((const int*)xraw)[(size_t)eb*TT + t];
        else       xv = ((const long long*)xraw)[(size_t)eb*TT + t];
        xv &= (VOC - 1);
        const float* Gb = g_G + (size_t)xv * G4H;
        float pgi = Gb[ej];
        float pgf = Gb[HID   + ej];
        float pgg = Gb[2*HID + ej];
        float pgo = Gb[3*HID + ej];

        // ---- 16 gate rows x 64 b dot products ----
        #pragma unroll 2
        for (int bi = 0; bi < 16; bi++){
            int b = bg*16 + bi;
            const char* hb = sm + b*2048;
            ull a0 = 0ull, a1 = 0ull, a2 = 0ull, a3 = 0ull;
            #pragma unroll
            for (int i = 0; i < 8; i++){
                ulonglong2 hv = *(const ulonglong2*)(hb + ((ks*8 + (i ^ ks7)) << 4));
                fma2(a0, hv.x, w0[2*i]); fma2(a0, hv.y, w0[2*i+1]);
                fma2(a1, hv.x, w1[2*i]); fma2(a1, hv.y, w1[2*i+1]);
                fma2(a2, hv.x, w2[2*i]); fma2(a2, hv.y, w2[2*i+1]);
                fma2(a3, hv.x, w3[2*i]); fma2(a3, hv.y, w3[2*i+1]);
            }
            float2 p;
            p = up2(a0); float s0 = redux16(p.x + p.y);
            p = up2(a1); float s1 = redux16(p.x + p.y);
            p = up2(a2); float s2 = redux16(p.x + p.y);
            p = up2(a3); float s3 = redux16(p.x + p.y);
            if (ks == 0)
                *(float4*)(gbuf + b*16 + gate*4) = make_float4(s0,s1,s2,s3);
        }
        __syncthreads();

        // ---- epilogue: activations, c/h update ----
        {
            float di = gbuf[eb*16 + 0  + ejj] + pgi;
            float df = gbuf[eb*16 + 4  + ejj] + pgf;
            float dg = gbuf[eb*16 + 8  + ejj] + pgg;
            float dv = gbuf[eb*16 + 12 + ejj] + pgo;
            float si = 1.f/(1.f + expf(-di));
            float sf = 1.f/(1.f + expf(-df));
            float tg = tanhf(dg);
            float so = 1.f/(1.f + expf(-dv));
            c_reg = sf * c_reg + si * tg;
            float h = so * tanhf(c_reg);
            g_h[(t+1) & 1][eb*HID + ej] = h;
            g_hs[((size_t)t*BB + eb)*HID + ej] = h;
        }

        // ---- grid barrier: release arrive + acquire poll ----
        __syncthreads();
        if (tid == 0){
            arrive_release(&g_ctr[t]);
            while (ld_acquire(&g_ctr[t]) < 128u) { }
        }
        __syncthreads();
    }
}

// ---------------- decode argmax, write predictions --------------------------
__global__ void writer_k(float* out, long long out_size){
    int m = blockIdx.x*blockDim.x + threadIdx.x;
    if (m >= BT) return;
    int idx = VOC - 1 - (int)(g_amax[m] & 0xFFFFFFFFull);
    int b = m & 63, tt = m >> 6;
    long long orow = (long long)b*TT + tt;
    if (out_size >= BTV + BT){
        out[BTV + orow] = (float)idx;              // logits + preds concatenated (f32)
    } else if (out_size < BTV && out_size >= BT){
        if (g_xmode) ((int*)out)[orow] = idx;      // preds-only, int32 world
        else ((long long*)out)[orow] = (long long)idx; // preds-only, int64 world
    }
}

extern "C" void kernel_launch(void* const* d_in, const int* in_sizes, int n_in,
                              void* d_out, int out_size)
{
    const void* x        = d_in[0];
    // d_in[1] = lens : unused by the reference computation
    const float* emb     = (const float*)d_in[2];
    const float* W_ih    = (const float*)d_in[3];
    const float* W_hh    = (const float*)d_in[4];
    const float* b_ih    = (const float*)d_in[5];
    const float* b_hh    = (const float*)d_in[6];
    const float* W_proj  = (const float*)d_in[7];
    const float* b_proj  = (const float*)d_in[8];
    (void)in_sizes; (void)n_in;

    float *pG, *pHS;
    cudaGetSymbolAddress((void**)&pG,  g_G);
    cudaGetSymbolAddress((void**)&pHS, g_hs);
    cudaFuncSetAttribute(lstm_k,
                         cudaFuncAttributeMaxDynamicSharedMemorySize, SM_LSTM);

    detect_k<<<1, 32>>>((const int*)x);
    init_k<<<256, 256>>>();

    // G = emb @ W_ih^T + (b_ih + b_hh)   [4096 x 2048], K=256
    gemm_k<<<dim3(VOC/128, G4H/128), 256>>>(emb, W_ih, b_ih, b_hh, pG,
                                            VOC, G4H, EMBD, /*flags=*/1);

    // persistent LSTM recurrence (single kernel, grid-wide barrier per step)
    lstm_k<<<128, 256, SM_LSTM>>>(x, W_hh);

    // logits = hs @ W_proj^T + b_proj    [65536 x 4096], K=512 (+ fused argmax)
    int flags = 4 | 2 | (((long long)out_size >= BTV) ? 1 : 0);
    gemm_k<<<dim3(BT/128, VOC/128), 256>>>(pHS, W_proj, b_proj, nullptr,
                                           (float*)d_out, BT, VOC, HID, flags);

    writer_k<<<BT/256, 256>>>((float*)d_out, (long long)out_size);
}

// round 13
// speedup vs baseline: 1.0992x; 1.0786x over previous
#include <cuda_runtime.h>
#include <cstdint>
#include <math.h>

#define VOC 4096
#define EMBD 256
#define HID 512
#define BB  64
#define TT  1024
#define G4H 2048
#define BT  (BB*TT)                       // 65536
#define BTV ((long long)BT*VOC)           // 268435456
#define HP  544                           // padded h row: 8 slices x 68 floats

typedef unsigned long long ull;

// ---------------- static device scratch (no runtime allocation) ----------------
__device__ __align__(16) float g_G[(size_t)VOC*G4H];   // 32 MB : emb@W_ih^T + (b_ih+b_hh)
__device__ __align__(16) float g_hs[(size_t)BT*HID];   // 128 MB: hidden states, row (t*64+b)
__device__ __align__(16) float g_hp[2][BB*HP];         // double-buffered h, slice-padded [b][8][68]
__device__ ull      g_amax[BT];                        // packed (float,idx) argmax per row
__device__ unsigned g_ctr[TT];                         // grid barrier arrival counters
__device__ int      g_xmode;                           // 1 = x is int32, 0 = x is int64

// ---------------- packed f32x2 + sync helpers ----------------
__device__ __forceinline__ void fma2(ull& d, ull a, ull b){
    asm("fma.rn.f32x2 %0, %1, %2, %0;" : "+l"(d) : "l"(a), "l"(b));
}
__device__ __forceinline__ ull pk2(float x, float y){
    ull r; asm("mov.b64 %0, {%1,%2};" : "=l"(r) : "f"(x), "f"(y)); return r;
}
__device__ __forceinline__ float2 up2(ull v){
    float2 r; asm("mov.b64 {%0,%1}, %2;" : "=f"(r.x), "=f"(r.y) : "l"(v)); return r;
}
__device__ __forceinline__ float hsum2(ull v){
    float2 p = up2(v); return p.x + p.y;
}
__device__ __forceinline__ float redux8(float v){
    v += __shfl_xor_sync(0xFFFFFFFFu, v, 1, 32);
    v += __shfl_xor_sync(0xFFFFFFFFu, v, 2, 32);
    v += __shfl_xor_sync(0xFFFFFFFFu, v, 4, 32);
    return v;
}
__device__ __forceinline__ void arrive_release(unsigned* p){
    asm volatile("red.release.gpu.global.add.u32 [%0], 1;" :: "l"(p) : "memory");
}
__device__ __forceinline__ unsigned ld_acquire(const unsigned* p){
    unsigned v; asm volatile("ld.acquire.gpu.global.u32 %0, [%1];" : "=r"(v) : "l"(p) : "memory");
    return v;
}
// monotone float->u32; pack with complemented index so max => (max val, lowest idx)
__device__ __forceinline__ ull packam(float v, int n){
    unsigned u = __float_as_uint(v);
    u = (u & 0x80000000u) ? ~u : (u | 0x80000000u);
    return ((ull)u << 32) | (unsigned)(VOC - 1 - n);
}

// ---------------- dtype detect + init (every replay) ----------------
__global__ void detect_k(const int* __restrict__ x32){
    if (threadIdx.x == 0){
        int nz = 0;
        for (int i = 0; i < 128; i++) nz += (x32[2*i + 1] != 0);
        g_xmode = (nz > 0) ? 1 : 0;   // all-odd-words-zero => little-endian int64 tokens
    }
}
__global__ void init_k(){
    int i = blockIdx.x*blockDim.x + threadIdx.x;
    int n = blockDim.x*gridDim.x;
    for (int p = i; p < BB*HP; p += n) g_hp[0][p] = 0.f;
    for (int p = i; p < BT;    p += n) g_amax[p] = 0ull;
    for (int p = i; p < TT;    p += n) g_ctr[p] = 0u;
}

// ---------------- SGEMM-NT with register double-buffering ----------------------
// BM=BN=128, BK=16, 256 threads, 8x8 micro-tile via f32x2.
// flags: 1 = write C, 2 = permute out row m -> (m%64)*TT + m/64, 4 = fused argmax
__global__ __launch_bounds__(256, 2) void gemm_k(
    const float* __restrict__ A, const float* __restrict__ B,
    const float* __restrict__ bias1, const float* __restrict__ bias2,
    float* __restrict__ C, int M, int N, int K, int flags)
{
    __shared__ __align__(16) float smem[2*16*132];
    float* As = smem;
    float* Bs = smem + 16*132;
    const int m0 = blockIdx.x*128, n0 = blockIdx.y*128;
    const int tid = threadIdx.x;
    const int tm = tid >> 4, tn = tid & 15;
    const int rowA = tid >> 2, kq = tid & 3;

    const float* Ap = A + (size_t)(m0 + rowA)*K + kq*4;
    const float* Bp = B + (size_t)(n0 + rowA)*K + kq*4;
    const size_t o64 = (size_t)64*K;

    ull acc[8][4];
    #pragma unroll
    for (int i = 0; i < 8; i++)
        #pragma unroll
        for (int j = 0; j < 4; j++) acc[i][j] = 0ull;

    // prologue: stage tile 0 into registers
    float4 va0 = *(const float4*)(Ap);
    float4 va1 = *(const float4*)(Ap + o64);
    float4 vb0 = *(const float4*)(Bp);
    float4 vb1 = *(const float4*)(Bp + o64);

    for (int kt = 0; kt < K; kt += 16){
        As[(kq*4+0)*132+rowA] = va0.x; As[(kq*4+1)*132+rowA] = va0.y;
        As[(kq*4+2)*132+rowA] = va0.z; As[(kq*4+3)*132+rowA] = va0.w;
        As[(kq*4+0)*132+rowA+64] = va1.x; As[(kq*4+1)*132+rowA+64] = va1.y;
        As[(kq*4+2)*132+rowA+64] = va1.z; As[(kq*4+3)*132+rowA+64] = va1.w;
        Bs[(kq*4+0)*132+rowA] = vb0.x; Bs[(kq*4+1)*132+rowA] = vb0.y;
        Bs[(kq*4+2)*132+rowA] = vb0.z; Bs[(kq*4+3)*132+rowA] = vb0.w;
        Bs[(kq*4+0)*132+rowA+64] = vb1.x; Bs[(kq*4+1)*132+rowA+64] = vb1.y;
        Bs[(kq*4+2)*132+rowA+64] = vb1.z; Bs[(kq*4+3)*132+rowA+64] = vb1.w;
        __syncthreads();

        if (kt + 16 < K){   // prefetch next tile (LDGs overlap the compute below)
            va0 = *(const float4*)(Ap + kt + 16);
            va1 = *(const float4*)(Ap + o64 + kt + 16);
            vb0 = *(const float4*)(Bp + kt + 16);
            vb1 = *(const float4*)(Bp + o64 + kt + 16);
        }

        #pragma unroll
        for (int k = 0; k < 16; k++){
            const float* ap = &As[k*132 + tm*8];
            float4 a0 = *(const float4*)ap;
            float4 a1 = *(const float4*)(ap + 4);
            const ulonglong2* bp = (const ulonglong2*)&Bs[k*132 + tn*8];
            ulonglong2 bq0 = bp[0], bq1 = bp[1];
            ull bb0 = bq0.x, bb1 = bq0.y, bb2 = bq1.x, bb3 = bq1.y;
            float aa[8] = {a0.x,a0.y,a0.z,a0.w,a1.x,a1.y,a1.z,a1.w};
            #pragma unroll
            for (int i = 0; i < 8; i++){
                ull ad = pk2(aa[i], aa[i]);
                fma2(acc[i][0], ad, bb0); fma2(acc[i][1], ad, bb1);
                fma2(acc[i][2], ad, bb2); fma2(acc[i][3], ad, bb3);
            }
        }
        __syncthreads();
    }

    float bv[8];
    {
        const float* b1p = bias1 + n0 + tn*8;
        #pragma unroll
        for (int c = 0; c < 8; c++) bv[c] = b1p[c];
        if (bias2){
            const float* b2p = bias2 + n0 + tn*8;
            #pragma unroll
            for (int c = 0; c < 8; c++) bv[c] += b2p[c];
        }
    }
    const bool wr = flags & 1, pm = flags & 2, am = flags & 4;
    ull best[8];
    #pragma unroll
    for (int i = 0; i < 8; i++){
        int m = m0 + tm*8 + i;
        float v[8];
        #pragma unroll
        for (int jp = 0; jp < 4; jp++){
            float2 f = up2(acc[i][jp]);
            v[2*jp]   = f.x + bv[2*jp];
            v[2*jp+1] = f.y + bv[2*jp+1];
        }
        if (wr){
            size_t orow = pm ? (size_t)((m & 63)*TT + (m >> 6)) : (size_t)m;
            float4* dst = (float4*)(C + orow*(size_t)N + n0 + tn*8);
            dst[0] = make_float4(v[0],v[1],v[2],v[3]);
            dst[1] = make_float4(v[4],v[5],v[6],v[7]);
        }
        if (am){
            ull bl = packam(v[0], n0 + tn*8);
            #pragma unroll
            for (int c = 1; c < 8; c++){
                ull p = packam(v[c], n0 + tn*8 + c);
                if (p > bl) bl = p;
            }
            best[i] = bl;
        }
    }
    if (am){
        __syncthreads();
        ull* red = (ull*)smem;               // 128*16 ull = 16384 B <= 16896 B
        #pragma unroll
        for (int i = 0; i < 8; i++) red[(tm*8+i)*16 + tn] = best[i];
        __syncthreads();
        if (tid < 128){
            ull b = red[tid*16];
            #pragma unroll
            for (int c = 1; c < 16; c++){
                ull p = red[tid*16 + c];
                if (p > b) b = p;
            }
            atomicMax(&g_amax[m0 + tid], b);
        }
    }
}

// ---------------- persistent LSTM recurrence: 128 blocks x 256 threads ----------
// Block = (jg in 32) x (bq in 4): 64 gate rows (16 j) x 16 batches.
// Thread = (rg in 32, ks in 8): 2 rows x 64 k in registers, 2 batches per pass.
// Stage: straight copy of this block's 16 b (35 KB) from slice-padded g_hp.
// Reduction: 3-level shfl over 8 k-lanes. Grid barrier: release/acquire.
#define SM_LSTM ((16*HP + 16*68)*4)      // 34816 + 4352 = 39168 B
__global__ __launch_bounds__(256, 1) void lstm_k(const void* __restrict__ xraw,
                                                 const float* __restrict__ Whh)
{
    extern __shared__ float hsm[];
    float* gbuf = hsm + 16*HP;           // [16 b][68] gate sums (rows 0..63 used)
    const int tid = threadIdx.x;
    const int jg  = blockIdx.x >> 2;     // 0..31 : j-group of 16
    const int bq  = blockIdx.x & 3;      // 0..3  : batch quarter of 16
    const int ks  = tid & 7;             // k-slice of 64
    const int rg  = tid >> 3;            // row-pair 0..31 (rows 2rg, 2rg+1 of 64)
    const int xmode = g_xmode;

    // ---- W_hh slice into registers (once): 2 rows x 64 k = 32+32 ull ----
    ull wa[32], wb[32];
    {
        int r0 = 2*rg, r1 = r0 + 1;
        int row0 = (r0 >> 4)*HID + jg*16 + (r0 & 15);   // gate*512 + j
        int row1 = (r1 >> 4)*HID + jg*16 + (r1 & 15);
        const float* p0 = Whh + (size_t)row0*HID + ks*64;
        const float* p1 = Whh + (size_t)row1*HID + ks*64;
        #pragma unroll
        for (int i = 0; i < 16; i++){
            float4 a = *(const float4*)(p0 + i*4);
            float4 b = *(const float4*)(p1 + i*4);
            wa[2*i] = pk2(a.x,a.y); wa[2*i+1] = pk2(a.z,a.w);
            wb[2*i] = pk2(b.x,b.y); wb[2*i+1] = pk2(b.z,b.w);
        }
    }

    // epilogue mapping: thread owns (b, j) every step -> c in register
    const int eb    = tid >> 4;                 // local b 0..15
    const int ejl   = tid & 15;                 // local j 0..15
    const int bglob = bq*16 + eb;
    const int jglob = jg*16 + ejl;
    float c_reg = 0.f;

    for (int t = 0; t < TT; t++){
        // ---- stage this block's 16 batches of h (straight float4 copy, L2) ----
        {
            const float4* src = (const float4*)(g_hp[t & 1] + (size_t)(bq*16)*HP);
            float4* dst = (float4*)hsm;
            #pragma unroll
            for (int l = 0; l < 9; l++){
                int i = tid + l*256;            // 16*544/4 = 2176 float4
                if (i < 2176) dst[i] = __ldcg(src + i);
            }
        }
        __syncthreads();

        // ---- prefetch token + gate-bias gather (consumed in epilogue) ----
        long long xv;
        if (xmode) xv = (long long)((const int*)xraw)[(size_t)bglob*TT + t];
        else       xv = ((const long long*)xraw)[(size_t)bglob*TT + t];
        xv &= (VOC - 1);
        const float* Gb = g_G + (size_t)xv * G4H + jglob;
        float pgi = Gb[0];
        float pgf = Gb[HID];
        float pgg = Gb[2*HID];
        float pgo = Gb[3*HID];

        // ---- 64 rows x 16 b: process batch-pairs ----
        #pragma unroll 1
        for (int bp = 0; bp < 8; bp++){
            const ulonglong2* h0 = (const ulonglong2*)(hsm + (2*bp  )*HP + ks*68);
            const ulonglong2* h1 = (const ulonglong2*)(hsm + (2*bp+1)*HP + ks*68);
            ull a00 = 0ull, a10 = 0ull, a01 = 0ull, a11 = 0ull;
            #pragma unroll
            for (int i = 0; i < 16; i++){
                ulonglong2 v0 = h0[i];
                fma2(a00, v0.x, wa[2*i]); fma2(a00, v0.y, wa[2*i+1]);
                fma2(a10, v0.x, wb[2*i]); fma2(a10, v0.y, wb[2*i+1]);
                ulonglong2 v1 = h1[i];
                fma2(a01, v1.x, wa[2*i]); fma2(a01, v1.y, wa[2*i+1]);
                fma2(a11, v1.x, wb[2*i]); fma2(a11, v1.y, wb[2*i+1]);
            }
            float s00 = redux8(hsum2(a00));
            float s10 = redux8(hsum2(a10));
            float s01 = redux8(hsum2(a01));
            float s11 = redux8(hsum2(a11));
            if (ks == 0){
                int r0 = 2*rg, r1 = r0 + 1;
                gbuf[(2*bp  )*68 + r0] = s00;
                gbuf[(2*bp  )*68 + r1] = s10;
                gbuf[(2*bp+1)*68 + r0] = s01;
                gbuf[(2*bp+1)*68 + r1] = s11;
            }
        }
        __syncthreads();

        // ---- epilogue: activations, c/h update (rows: gate*16 + jloc) ----
        {
            float di = gbuf[eb*68 +  0 + ejl] + pgi;
            float df = gbuf[eb*68 + 16 + ejl] + pgf;
            float dg = gbuf[eb*68 + 32 + ejl] + pgg;
            float dv = gbuf[eb*68 + 48 + ejl] + pgo;
            float si = 1.f/(1.f + expf(-di));
            float sf = 1.f/(1.f + expf(-df));
            float tg = tanhf(dg);
            float so = 1.f/(1.f + expf(-dv));
            c_reg = sf * c_reg + si * tg;
            float h = so * tanhf(c_reg);
            g_hs[((size_t)t*BB + bglob)*HID + jglob] = h;
            g_hp[(t+1) & 1][(size_t)bglob*HP + (jglob >> 6)*68 + (jglob & 63)] = h;
        }

        // ---- grid barrier: release arrive + acquire poll ----
        __syncthreads();
        if (tid == 0){
            arrive_release(&g_ctr[t]);
            while (ld_acquire(&g_ctr[t]) < 128u) { }
        }
        __syncthreads();
    }
}

// ---------------- decode argmax, write predictions --------------------------
__global__ void writer_k(float* out, long long out_size){
    int m = blockIdx.x*blockDim.x + threadIdx.x;
    if (m >= BT) return;
    int idx = VOC - 1 - (int)(g_amax[m] & 0xFFFFFFFFull);
    int b = m & 63, tt = m >> 6;
    long long orow = (long long)b*TT + tt;
    if (out_size >= BTV + BT){
        out[BTV + orow] = (float)idx;              // logits + preds concatenated (f32)
    } else if (out_size < BTV && out_size >= BT){
        if (g_xmode) ((int*)out)[orow] = idx;      // preds-only, int32 world
        else ((long long*)out)[orow] = (long long)idx; // preds-only, int64 world
    }
}

extern "C" void kernel_launch(void* const* d_in, const int* in_sizes, int n_in,
                              void* d_out, int out_size)
{
    const void* x        = d_in[0];
    // d_in[1] = lens : unused by the reference computation
    const float* emb     = (const float*)d_in[2];
    const float* W_ih    = (const float*)d_in[3];
    const float* W_hh    = (const float*)d_in[4];
    const float* b_ih    = (const float*)d_in[5];
    const float* b_hh    = (const float*)d_in[6];
    const float* W_proj  = (const float*)d_in[7];
    const float* b_proj  = (const float*)d_in[8];
    (void)in_sizes; (void)n_in;

    float *pG, *pHS;
    cudaGetSymbolAddress((void**)&pG,  g_G);
    cudaGetSymbolAddress((void**)&pHS, g_hs);
    cudaFuncSetAttribute(lstm_k,
                         cudaFuncAttributeMaxDynamicSharedMemorySize, SM_LSTM);

    detect_k<<<1, 32>>>((const int*)x);
    init_k<<<256, 256>>>();

    // G = emb @ W_ih^T + (b_ih + b_hh)   [4096 x 2048], K=256
    gemm_k<<<dim3(VOC/128, G4H/128), 256>>>(emb, W_ih, b_ih, b_hh, pG,
                                            VOC, G4H, EMBD, /*flags=*/1);

    // persistent LSTM recurrence (single kernel, grid-wide barrier per step)
    lstm_k<<<128, 256, SM_LSTM>>>(x, W_hh);

    // logits = hs @ W_proj^T + b_proj    [65536 x 4096], K=512 (+ fused argmax)
    int flags = 4 | 2 | (((long long)out_size >= BTV) ? 1 : 0);
    gemm_k<<<dim3(BT/128, VOC/128), 256>>>(pHS, W_proj, b_proj, nullptr,
                                           (float*)d_out, BT, VOC, HID, flags);

    writer_k<<<BT/256, 256>>>((float*)d_out, (long long)out_size);
}

// round 14
// speedup vs baseline: 1.1253x; 1.0237x over previous
#include <cuda_runtime.h>
#include <cstdint>
#include <math.h>

#define VOC 4096
#define EMBD 256
#define HID 512
#define BB  64
#define TT  1024
#define G4H 2048
#define BT  (BB*TT)                       // 65536
#define BTV ((long long)BT*VOC)           // 268435456
#define HP  544                           // padded h row: 8 slices x 68 floats

typedef unsigned long long ull;

// ---------------- static device scratch (no runtime allocation) ----------------
__device__ __align__(16) float g_G[(size_t)VOC*G4H];   // 32 MB : emb@W_ih^T + (b_ih+b_hh)
__device__ __align__(16) float g_hs[(size_t)BT*HID];   // 128 MB: hidden states, row (t*64+b)
__device__ __align__(16) float g_hp[2][BB*HP];         // double-buffered h, slice-padded [b][8][68]
__device__ ull      g_amax[BT];                        // packed (float,idx) argmax per row
__device__ unsigned g_ctr[4*TT];                       // per-batch-quarter barrier counters
__device__ int      g_xmode;                           // 1 = x is int32, 0 = x is int64

// ---------------- packed f32x2 + sync helpers ----------------
__device__ __forceinline__ void fma2(ull& d, ull a, ull b){
    asm("fma.rn.f32x2 %0, %1, %2, %0;" : "+l"(d) : "l"(a), "l"(b));
}
__device__ __forceinline__ ull pk2(float x, float y){
    ull r; asm("mov.b64 %0, {%1,%2};" : "=l"(r) : "f"(x), "f"(y)); return r;
}
__device__ __forceinline__ float2 up2(ull v){
    float2 r; asm("mov.b64 {%0,%1}, %2;" : "=f"(r.x), "=f"(r.y) : "l"(v)); return r;
}
__device__ __forceinline__ float hsum2(ull v){
    float2 p = up2(v); return p.x + p.y;
}
__device__ __forceinline__ float redux8(float v){
    v += __shfl_xor_sync(0xFFFFFFFFu, v, 1, 32);
    v += __shfl_xor_sync(0xFFFFFFFFu, v, 2, 32);
    v += __shfl_xor_sync(0xFFFFFFFFu, v, 4, 32);
    return v;
}
__device__ __forceinline__ void arrive_release(unsigned* p){
    asm volatile("red.release.gpu.global.add.u32 [%0], 1;" :: "l"(p) : "memory");
}
__device__ __forceinline__ unsigned ld_acquire(const unsigned* p){
    unsigned v; asm volatile("ld.acquire.gpu.global.u32 %0, [%1];" : "=r"(v) : "l"(p) : "memory");
    return v;
}
// monotone float->u32; pack with complemented index so max => (max val, lowest idx)
__device__ __forceinline__ ull packam(float v, int n){
    unsigned u = __float_as_uint(v);
    u = (u & 0x80000000u) ? ~u : (u | 0x80000000u);
    return ((ull)u << 32) | (unsigned)(VOC - 1 - n);
}

// ---------------- dtype detect + init (every replay) ----------------
__global__ void detect_k(const int* __restrict__ x32){
    if (threadIdx.x == 0){
        int nz = 0;
        for (int i = 0; i < 128; i++) nz += (x32[2*i + 1] != 0);
        g_xmode = (nz > 0) ? 1 : 0;   // all-odd-words-zero => little-endian int64 tokens
    }
}
__global__ void init_k(){
    int i = blockIdx.x*blockDim.x + threadIdx.x;
    int n = blockDim.x*gridDim.x;
    for (int p = i; p < BB*HP; p += n) g_hp[0][p] = 0.f;
    for (int p = i; p < BT;    p += n) g_amax[p] = 0ull;
    for (int p = i; p < 4*TT;  p += n) g_ctr[p] = 0u;
}

// ---------------- SGEMM-NT: double-buffered smem + register prefetch -----------
// BM=BN=128, BK=16, 256 threads, 8x8 micro-tile via f32x2. ONE sync per k-tile.
// flags: 1 = write C, 2 = permute out row m -> (m%64)*TT + m/64, 4 = fused argmax
__global__ __launch_bounds__(256, 2) void gemm_k(
    const float* __restrict__ A, const float* __restrict__ B,
    const float* __restrict__ bias1, const float* __restrict__ bias2,
    float* __restrict__ C, int M, int N, int K, int flags)
{
    __shared__ __align__(16) float smem[2][4224];   // per buffer: As 2112 | Bs 2112
    const int m0 = blockIdx.x*128, n0 = blockIdx.y*128;
    const int tid = threadIdx.x;
    const int tm = tid >> 4, tn = tid & 15;
    const int rowA = tid >> 2, kq = tid & 3;

    const float* Ap = A + (size_t)(m0 + rowA)*K + kq*4;
    const float* Bp = B + (size_t)(n0 + rowA)*K + kq*4;
    const size_t o64 = (size_t)64*K;

    ull acc[8][4];
    #pragma unroll
    for (int i = 0; i < 8; i++)
        #pragma unroll
        for (int j = 0; j < 4; j++) acc[i][j] = 0ull;

    // prologue: stage tile 0 into registers
    float4 va0 = *(const float4*)(Ap);
    float4 va1 = *(const float4*)(Ap + o64);
    float4 vb0 = *(const float4*)(Bp);
    float4 vb1 = *(const float4*)(Bp + o64);

    int cur = 0;
    for (int kt = 0; kt < K; kt += 16){
        float* As = smem[cur];
        float* Bs = smem[cur] + 2112;
        As[(kq*4+0)*132+rowA] = va0.x; As[(kq*4+1)*132+rowA] = va0.y;
        As[(kq*4+2)*132+rowA] = va0.z; As[(kq*4+3)*132+rowA] = va0.w;
        As[(kq*4+0)*132+rowA+64] = va1.x; As[(kq*4+1)*132+rowA+64] = va1.y;
        As[(kq*4+2)*132+rowA+64] = va1.z; As[(kq*4+3)*132+rowA+64] = va1.w;
        Bs[(kq*4+0)*132+rowA] = vb0.x; Bs[(kq*4+1)*132+rowA] = vb0.y;
        Bs[(kq*4+2)*132+rowA] = vb0.z; Bs[(kq*4+3)*132+rowA] = vb0.w;
        Bs[(kq*4+0)*132+rowA+64] = vb1.x; Bs[(kq*4+1)*132+rowA+64] = vb1.y;
        Bs[(kq*4+2)*132+rowA+64] = vb1.z; Bs[(kq*4+3)*132+rowA+64] = vb1.w;
        __syncthreads();

        if (kt + 16 < K){   // prefetch next tile (LDGs overlap the compute below)
            va0 = *(const float4*)(Ap + kt + 16);
            va1 = *(const float4*)(Ap + o64 + kt + 16);
            vb0 = *(const float4*)(Bp + kt + 16);
            vb1 = *(const float4*)(Bp + o64 + kt + 16);
        }

        #pragma unroll
        for (int k = 0; k < 16; k++){
            const float* ap = &As[k*132 + tm*8];
            float4 a0 = *(const float4*)ap;
            float4 a1 = *(const float4*)(ap + 4);
            const ulonglong2* bp = (const ulonglong2*)&Bs[k*132 + tn*8];
            ulonglong2 bq0 = bp[0], bq1 = bp[1];
            ull bb0 = bq0.x, bb1 = bq0.y, bb2 = bq1.x, bb3 = bq1.y;
            float aa[8] = {a0.x,a0.y,a0.z,a0.w,a1.x,a1.y,a1.z,a1.w};
            #pragma unroll
            for (int i = 0; i < 8; i++){
                ull ad = pk2(aa[i], aa[i]);
                fma2(acc[i][0], ad, bb0); fma2(acc[i][1], ad, bb1);
                fma2(acc[i][2], ad, bb2); fma2(acc[i][3], ad, bb3);
            }
        }
        cur ^= 1;           // next tile writes the other buffer (no second sync)
    }

    float bv[8];
    {
        const float* b1p = bias1 + n0 + tn*8;
        #pragma unroll
        for (int c = 0; c < 8; c++) bv[c] = b1p[c];
        if (bias2){
            const float* b2p = bias2 + n0 + tn*8;
            #pragma unroll
            for (int c = 0; c < 8; c++) bv[c] += b2p[c];
        }
    }
    const bool wr = flags & 1, pm = flags & 2, am = flags & 4;
    ull best[8];
    #pragma unroll
    for (int i = 0; i < 8; i++){
        int m = m0 + tm*8 + i;
        float v[8];
        #pragma unroll
        for (int jp = 0; jp < 4; jp++){
            float2 f = up2(acc[i][jp]);
            v[2*jp]   = f.x + bv[2*jp];
            v[2*jp+1] = f.y + bv[2*jp+1];
        }
        if (wr){
            size_t orow = pm ? (size_t)((m & 63)*TT + (m >> 6)) : (size_t)m;
            float4* dst = (float4*)(C + orow*(size_t)N + n0 + tn*8);
            dst[0] = make_float4(v[0],v[1],v[2],v[3]);
            dst[1] = make_float4(v[4],v[5],v[6],v[7]);
        }
        if (am){
            ull bl = packam(v[0], n0 + tn*8);
            #pragma unroll
            for (int c = 1; c < 8; c++){
                ull p = packam(v[c], n0 + tn*8 + c);
                if (p > bl) bl = p;
            }
            best[i] = bl;
        }
    }
    if (am){
        __syncthreads();
        ull* red = (ull*)&smem[0][0];        // 128*16 ull = 16384 B fits buffer 0
        #pragma unroll
        for (int i = 0; i < 8; i++) red[(tm*8+i)*16 + tn] = best[i];
        __syncthreads();
        if (tid < 128){
            ull b = red[tid*16];
            #pragma unroll
            for (int c = 1; c < 16; c++){
                ull p = red[tid*16 + c];
                if (p > b) b = p;
            }
            atomicMax(&g_amax[m0 + tid], b);
        }
    }
}

// ---------------- persistent LSTM recurrence: 128 blocks x 256 threads ----------
// Block = (jg in 32) x (bq in 4): 64 gate rows (16 j) x 16 batches.
// The 4 batch-quarters are fully independent chains -> per-bq 32-arrival barrier.
// Thread = (rg in 32, ks in 8): 2 rows x 64 k of W_hh in registers.
#define SM_LSTM ((16*HP + 16*68)*4)      // 34816 + 4352 = 39168 B
__global__ __launch_bounds__(256, 1) void lstm_k(const void* __restrict__ xraw,
                                                 const float* __restrict__ Whh)
{
    extern __shared__ float hsm[];
    float* gbuf = hsm + 16*HP;           // [16 b][68] gate sums (rows 0..63 used)
    const int tid = threadIdx.x;
    const int jg  = blockIdx.x >> 2;     // 0..31 : j-group of 16
    const int bq  = blockIdx.x & 3;      // 0..3  : batch quarter of 16
    const int ks  = tid & 7;             // k-slice of 64
    const int rg  = tid >> 3;            // row-pair 0..31 (rows 2rg, 2rg+1 of 64)
    const int xmode = g_xmode;
    unsigned* ctr = g_ctr + bq*TT;       // this quarter's barrier counters

    // ---- W_hh slice into registers (once): 2 rows x 64 k = 32+32 ull ----
    ull wa[32], wb[32];
    {
        int r0 = 2*rg, r1 = r0 + 1;
        int row0 = (r0 >> 4)*HID + jg*16 + (r0 & 15);   // gate*512 + j
        int row1 = (r1 >> 4)*HID + jg*16 + (r1 & 15);
        const float* p0 = Whh + (size_t)row0*HID + ks*64;
        const float* p1 = Whh + (size_t)row1*HID + ks*64;
        #pragma unroll
        for (int i = 0; i < 16; i++){
            float4 a = *(const float4*)(p0 + i*4);
            float4 b = *(const float4*)(p1 + i*4);
            wa[2*i] = pk2(a.x,a.y); wa[2*i+1] = pk2(a.z,a.w);
            wb[2*i] = pk2(b.x,b.y); wb[2*i+1] = pk2(b.z,b.w);
        }
    }

    // epilogue mapping: thread owns (b, j) every step -> c in register
    const int eb    = tid >> 4;                 // local b 0..15
    const int ejl   = tid & 15;                 // local j 0..15
    const int bglob = bq*16 + eb;
    const int jglob = jg*16 + ejl;
    float c_reg = 0.f;

    for (int t = 0; t < TT; t++){
        // ---- stage this block's 16 batches of h (straight float4 copy, L2) ----
        {
            const float4* src = (const float4*)(g_hp[t & 1] + (size_t)(bq*16)*HP);
            float4* dst = (float4*)hsm;
            #pragma unroll
            for (int l = 0; l < 9; l++){
                int i = tid + l*256;            // 16*544/4 = 2176 float4
                if (i < 2176) dst[i] = __ldcg(src + i);
            }
        }
        __syncthreads();

        // ---- prefetch token + gate-bias gather (consumed in epilogue) ----
        long long xv;
        if (xmode) xv = (long long)((const int*)xraw)[(size_t)bglob*TT + t];
        else       xv = ((const long long*)xraw)[(size_t)bglob*TT + t];
        xv &= (VOC - 1);
        const float* Gb = g_G + (size_t)xv * G4H + jglob;
        float pgi = Gb[0];
        float pgf = Gb[HID];
        float pgg = Gb[2*HID];
        float pgo = Gb[3*HID];

        // ---- 64 rows x 16 b: process batch-pairs ----
        #pragma unroll 1
        for (int bp = 0; bp < 8; bp++){
            const ulonglong2* h0 = (const ulonglong2*)(hsm + (2*bp  )*HP + ks*68);
            const ulonglong2* h1 = (const ulonglong2*)(hsm + (2*bp+1)*HP + ks*68);
            ull a00 = 0ull, a10 = 0ull, a01 = 0ull, a11 = 0ull;
            #pragma unroll
            for (int i = 0; i < 16; i++){
                ulonglong2 v0 = h0[i];
                fma2(a00, v0.x, wa[2*i]); fma2(a00, v0.y, wa[2*i+1]);
                fma2(a10, v0.x, wb[2*i]); fma2(a10, v0.y, wb[2*i+1]);
                ulonglong2 v1 = h1[i];
                fma2(a01, v1.x, wa[2*i]); fma2(a01, v1.y, wa[2*i+1]);
                fma2(a11, v1.x, wb[2*i]); fma2(a11, v1.y, wb[2*i+1]);
            }
            float s00 = redux8(hsum2(a00));
            float s10 = redux8(hsum2(a10));
            float s01 = redux8(hsum2(a01));
            float s11 = redux8(hsum2(a11));
            if (ks == 0){
                int r0 = 2*rg, r1 = r0 + 1;
                gbuf[(2*bp  )*68 + r0] = s00;
                gbuf[(2*bp  )*68 + r1] = s10;
                gbuf[(2*bp+1)*68 + r0] = s01;
                gbuf[(2*bp+1)*68 + r1] = s11;
            }
        }
        __syncthreads();

        // ---- epilogue: activations, c/h update (rows: gate*16 + jloc) ----
        {
            float di = gbuf[eb*68 +  0 + ejl] + pgi;
            float df = gbuf[eb*68 + 16 + ejl] + pgf;
            float dg = gbuf[eb*68 + 32 + ejl] + pgg;
            float dv = gbuf[eb*68 + 48 + ejl] + pgo;
            float si = 1.f/(1.f + expf(-di));
            float sf = 1.f/(1.f + expf(-df));
            float tg = tanhf(dg);
            float so = 1.f/(1.f + expf(-dv));
            c_reg = sf * c_reg + si * tg;
            float h = so * tanhf(c_reg);
            g_hs[((size_t)t*BB + bglob)*HID + jglob] = h;
            g_hp[(t+1) & 1][(size_t)bglob*HP + (jglob >> 6)*68 + (jglob & 63)] = h;
        }

        // ---- per-quarter barrier (32 arrivals): release arrive + acquire poll ----
        __syncthreads();
        if (tid == 0){
            arrive_release(&ctr[t]);
            while (ld_acquire(&ctr[t]) < 32u) { }
        }
        __syncthreads();
    }
}

// ---------------- decode argmax, write predictions --------------------------
__global__ void writer_k(float* out, long long out_size){
    int m = blockIdx.x*blockDim.x + threadIdx.x;
    if (m >= BT) return;
    int idx = VOC - 1 - (int)(g_amax[m] & 0xFFFFFFFFull);
    int b = m & 63, tt = m >> 6;
    long long orow = (long long)b*TT + tt;
    if (out_size >= BTV + BT){
        out[BTV + orow] = (float)idx;              // logits + preds concatenated (f32)
    } else if (out_size < BTV && out_size >= BT){
        if (g_xmode) ((int*)out)[orow] = idx;      // preds-only, int32 world
        else ((long long*)out)[orow] = (long long)idx; // preds-only, int64 world
    }
}

extern "C" void kernel_launch(void* const* d_in, const int* in_sizes, int n_in,
                              void* d_out, int out_size)
{
    const void* x        = d_in[0];
    // d_in[1] = lens : unused by the reference computation
    const float* emb     = (const float*)d_in[2];
    const float* W_ih    = (const float*)d_in[3];
    const float* W_hh    = (const float*)d_in[4];
    const float* b_ih    = (const float*)d_in[5];
    const float* b_hh    = (const float*)d_in[6];
    const float* W_proj  = (const float*)d_in[7];
    const float* b_proj  = (const float*)d_in[8];
    (void)in_sizes; (void)n_in;

    float *pG, *pHS;
    cudaGetSymbolAddress((void**)&pG,  g_G);
    cudaGetSymbolAddress((void**)&pHS, g_hs);
    cudaFuncSetAttribute(lstm_k,
                         cudaFuncAttributeMaxDynamicSharedMemorySize, SM_LSTM);

    detect_k<<<1, 32>>>((const int*)x);
    init_k<<<256, 256>>>();

    // G = emb @ W_ih^T + (b_ih + b_hh)   [4096 x 2048], K=256
    gemm_k<<<dim3(VOC/128, G4H/128), 256>>>(emb, W_ih, b_ih, b_hh, pG,
                                            VOC, G4H, EMBD, /*flags=*/1);

    // persistent LSTM recurrence (single kernel, per-quarter barriers)
    lstm_k<<<128, 256, SM_LSTM>>>(x, W_hh);

    // logits = hs @ W_proj^T + b_proj    [65536 x 4096], K=512 (+ fused argmax)
    int flags = 4 | 2 | (((long long)out_size >= BTV) ? 1 : 0);
    gemm_k<<<dim3(BT/128, VOC/128), 256>>>(pHS, W_proj, b_proj, nullptr,
                                           (float*)d_out, BT, VOC, HID, flags);

    writer_k<<<BT/256, 256>>>((float*)d_out, (long long)out_size);
}